// round 14
// baseline (speedup 1.0000x reference)
#include <cuda_runtime.h>
#include <cuda_fp16.h>
#include <cstdint>

#define N_HEADS 4
#define H_DIM   128
#define TOK_F   512
#define K_DIM   4096
#define BLK     32
#define STRIDE  16
#define MAXSEQ  256
#define MAXTILE 8192

#define A_SLOT  17408           // 2(dh) x 68 rows x 128B
#define TOK_OFF (2 * A_SLOT)
#define SMEM_GEMM (TOK_OFF + 128)

// ---------------- device scratch ----------------
__device__ int    g_total_out;
__device__ int    g_ntiles;
__device__ int    g_tile_o0[MAXTILE];
__device__ int    g_tile_tok0[MAXTILE];
__device__ int    g_tile_lim[MAXTILE];
__device__ int    g_tile_nrow[MAXTILE];
// B in MMA fragment order: [mat][(atom*256 + chunk)*32 + lane] = {b0,b1}
__device__ uint2  g_wB[2][131072];

static __device__ __forceinline__ uint32_t smem_u32(const void* p) {
    uint32_t a;
    asm("{ .reg .u64 t; cvta.to.shared.u64 t, %1; cvt.u32.u64 %0, t; }" : "=r"(a) : "l"(p));
    return a;
}

#define LDMATRIX_X4(r0, r1, r2, r3, addr) \
    asm volatile("ldmatrix.sync.aligned.m8n8.x4.shared.b16 {%0,%1,%2,%3}, [%4];" \
                 : "=r"(r0), "=r"(r1), "=r"(r2), "=r"(r3) : "r"(addr))

// fp16-accumulate MMA: D,C packed half2 x2
#define MMAF16(c, a0, a1, a2, a3, b0, b1) \
    asm volatile("mma.sync.aligned.m16n8k16.row.col.f16.f16.f16.f16 " \
                 "{%0,%1}, {%2,%3,%4,%5}, {%6,%7}, {%0,%1};" \
                 : "+r"((c)[0]), "+r"((c)[1]) \
                 : "r"(a0), "r"(a1), "r"(a2), "r"(a3), "r"(b0), "r"(b1))

// substep u -> base k16 chunk: j = T + 16*(sub>>1), dh = sub&1
static __device__ __forceinline__ int cb_of(int u) {
    return (u >> 2) * 8 + ((u & 2) << 6) + (u & 1) * 4;
}
// global MMA round g (= u*4 + k16i) -> chunk index
static __device__ __forceinline__ int chunk_of_round(int g) {
    if (g > 255) g = 255;
    return cb_of(g >> 2) + (g & 3);
}

// ---------------- kernel 1: prep = metadata/tile-table + W fragment pack ----------------
__global__ void prep_kernel(const int* __restrict__ cu, int nseq,
                            const float* __restrict__ wk, const float* __restrict__ wv,
                            float* __restrict__ dout) {
    int t = threadIdx.y * 32 + threadIdx.x;
    if (blockIdx.x == 1024) {
        __shared__ int s_ol[MAXSEQ];
        __shared__ int s_cu[MAXSEQ + 1];
        __shared__ int s_ts[MAXSEQ + 1];
        if (t < nseq) {
            int n = cu[t + 1] - cu[t];
            s_ol[t] = (n >= BLK) ? (n - BLK) / STRIDE : 0;
        }
        __syncthreads();
        if (t == 0) {
            int acc = 0, tacc = 0;
            s_cu[0] = 0; s_ts[0] = 0;
            for (int b = 0; b < nseq; b++) {
                acc += s_ol[b];
                tacc += (s_ol[b] + 15) >> 4;
                s_cu[b + 1] = acc;
                s_ts[b + 1] = tacc;
            }
            g_total_out = acc;
            g_ntiles = tacc;
        }
        __syncthreads();
        int total = s_cu[nseq];
        int ntl = s_ts[nseq];
        for (int i = t; i <= nseq; i += 256)
            dout[(size_t)2 * total * 512 + i] = (float)s_cu[i];
        for (int x = t; x < ntl; x += 256) {
            int b = 0;
            while (s_ts[b + 1] <= x) b++;
            int ti = x - s_ts[b];
            int o0 = s_cu[b] + ti * 16;
            int ol = s_cu[b + 1] - o0;
            g_tile_o0[x]   = o0;
            g_tile_tok0[x] = cu[b] + ti * 256;
            g_tile_lim[x]  = cu[b + 1] - 16;
            g_tile_nrow[x] = (ol < 16 ? ol : 16) * 4;
        }
        return;
    }
    // fragment-pack W: idx -> (atom a, chunk c, lane l)
    int z   = blockIdx.x >> 9;
    int rem = blockIdx.x & 511;
    const float* w = z ? wv : wk;
    int idx = rem * 256 + t;                  // 0..131071
    int a = idx >> 13;
    int c = (idx >> 5) & 255;
    int l = idx & 31;
    int n  = 8 * a + (l >> 2);
    int k1 = 16 * c + 2 * (l & 3);
    float v0 = w[(size_t)k1 * H_DIM + n];
    float v1 = w[(size_t)(k1 + 1) * H_DIM + n];
    float v2 = w[(size_t)(k1 + 8) * H_DIM + n];
    float v3 = w[(size_t)(k1 + 9) * H_DIM + n];
    __half2 h0 = __floats2half2_rn(v0, v1);
    __half2 h1 = __floats2half2_rn(v2, v3);
    uint2 u;
    u.x = *reinterpret_cast<uint32_t*>(&h0);
    u.y = *reinterpret_cast<uint32_t*>(&h1);
    g_wB[z][idx] = u;
}

// ---------------- kernel 2: HMMA GEMM, B direct-from-L2, 3 CTAs/SM ----------------
// 256 thr = 8 warps in 2(M) x 4(N); warp tile 32x32; CTA tile 64x128.
// A: token-dedup smem staging, one __syncthreads per superstep.
// B: LDG.64 fragments in a 2-round register ring (parity = k16i&1).
__global__ __launch_bounds__(256, 3)
void gemm_kernel(const float* __restrict__ kin, const float* __restrict__ vin,
                 float* __restrict__ dout) {
    extern __shared__ __align__(128) char smem[];
    const uint32_t sa = smem_u32(smem);            // A: 2 slots x 17408
    int* s_tok = (int*)(smem + TOK_OFF);

    const int tid = threadIdx.x;
    const int wid = tid >> 5;
    const int lid = tid & 31;
    const int bx  = blockIdx.x;
    if (bx >= g_ntiles) return;
    const int total_out = g_total_out;
    const int o0   = g_tile_o0[bx];
    const int tok0 = g_tile_tok0[bx];
    const int lim  = g_tile_lim[bx];
    const int nrow = g_tile_nrow[bx];

    const int mat = blockIdx.y;
    const float* __restrict__ x = mat ? vin : kin;
    const uint2* __restrict__ wB = g_wB[mat];
    float* __restrict__ outp = dout + (size_t)mat * (size_t)total_out * 512;

    if (tid < 17) {
        int tk = tok0 + 16 * tid;
        s_tok[tid] = tk < lim ? tk : lim;
    }
    __syncthreads();

    // ---- A staging tasks: tau = sr*8 + dh*4 + cpair ----
    int      sgoff[3];
    uint32_t sadr[3];
    const int ntask3 = (tid < 32) ? 1 : 0;
#pragma unroll
    for (int tsk = 0; tsk < 3; tsk++) {
        int tau = tsk * 256 + tid;
        if (tau >= 544) tau = 543;
        int sr = tau >> 3, dh = (tau >> 2) & 1, cp = tau & 3;
        int i = sr >> 2, h = sr & 3;
        sgoff[tsk] = s_tok[i] * TOK_F + h * H_DIM + dh * 64 + cp * 16;
        sadr[tsk]  = (uint32_t)(dh * 8704 + sr * 128 + (((2 * cp) ^ (sr & 7)) * 16));
    }

    // ---- ldmatrix A addresses ----
    const int wr = wid >> 2;       // M position 0..1
    const int wc = wid & 3;        // N position 0..3
    const int g  = lid >> 3;
    const int l7 = lid & 7;
    uint32_t lma[2][4];
    int hidelta[4];
#pragma unroll
    for (int k16i = 0; k16i < 4; k16i++) {
        int c = 2 * k16i + (g >> 1);
        hidelta[k16i] = 512 + (((c ^ l7) & 4) ? -64 : 64);
#pragma unroll
        for (int ma = 0; ma < 2; ma++) {
            int sr = wr * 32 + ma * 16 + (g & 1) * 8 + l7;
            lma[ma][k16i] = sa + (uint32_t)(sr * 128 + ((c ^ (sr & 7)) * 16));
        }
    }

    // ---- B fragment element bases: atom a = wc*4 + p ----
    int bbase[4];
#pragma unroll
    for (int p = 0; p < 4; p++)
        bbase[p] = ((wc * 4 + p) << 13) + lid;

    float acc[2][4][4];
    uint32_t facc[2][4][2];
#pragma unroll
    for (int ma = 0; ma < 2; ma++)
#pragma unroll
        for (int na = 0; na < 4; na++) {
#pragma unroll
            for (int e = 0; e < 4; e++) acc[ma][na][e] = 0.f;
            facc[ma][na][0] = 0u; facc[ma][na][1] = 0u;
        }

    // staging task: 16 fp32 LDG -> cvt -> 2 swizzled uint4 STS
    auto run_task = [&](int tsk, int jnext, uint32_t abuf) {
        const float* p = x + sgoff[tsk] + jnext * TOK_F;
        float4 f0 = *(const float4*)(p);
        float4 f1 = *(const float4*)(p + 4);
        float4 f2 = *(const float4*)(p + 8);
        float4 f3 = *(const float4*)(p + 12);
        __half2 h;
        uint4 u1, u2;
        h = __floats2half2_rn(f0.x, f0.y); u1.x = *(uint32_t*)&h;
        h = __floats2half2_rn(f0.z, f0.w); u1.y = *(uint32_t*)&h;
        h = __floats2half2_rn(f1.x, f1.y); u1.z = *(uint32_t*)&h;
        h = __floats2half2_rn(f1.z, f1.w); u1.w = *(uint32_t*)&h;
        h = __floats2half2_rn(f2.x, f2.y); u2.x = *(uint32_t*)&h;
        h = __floats2half2_rn(f2.z, f2.w); u2.y = *(uint32_t*)&h;
        h = __floats2half2_rn(f3.x, f3.y); u2.z = *(uint32_t*)&h;
        h = __floats2half2_rn(f3.z, f3.w); u2.w = *(uint32_t*)&h;
        uint32_t a1 = abuf + sadr[tsk];
        *(uint4*)(smem + a1) = u1;
        *(uint4*)(smem + (a1 ^ 16)) = u2;
    };

    // ---- prologue: stage A superstep 0; preload B round 0 into ring slot 0 ----
    run_task(0, 0, 0);
    run_task(1, 0, 0);
    if (ntask3) run_task(2, 0, 0);

    uint2 bb[2][4];                            // 2-round B ring; parity = k16i&1
    {
        const int c0 = chunk_of_round(0);
#pragma unroll
        for (int p = 0; p < 4; p++)
            bb[0][p] = wB[bbase[p] + c0 * 32];
    }

#pragma unroll 1
    for (int T = 0; T < 16; T++) {
        __syncthreads();   // publish A slot T&1; slot (T+1)&1 free (readers were T-1)
        const uint32_t ab  = (uint32_t)((T & 1) * A_SLOT);
        const uint32_t abn = (uint32_t)(((T + 1) & 1) * A_SLOT);
        const int stage_ok = (T + 1 < 16);

#pragma unroll
        for (int sub = 0; sub < 4; sub++) {
            const int u = T * 4 + sub;
            const uint32_t adh = ab + (uint32_t)((sub & 1) * 8704);
            const int hi = sub >> 1;

#pragma unroll
            for (int k16i = 0; k16i < 4; k16i++) {
                const int cur = k16i & 1;           // static ring parity
                // prefetch round g+1 into the other slot
                {
                    const int cn = chunk_of_round(u * 4 + k16i + 1);
#pragma unroll
                    for (int p = 0; p < 4; p++)
                        bb[cur ^ 1][p] = wB[bbase[p] + cn * 32];
                }
                uint32_t adel = adh + (hi ? (uint32_t)hidelta[k16i] : 0u);
                uint32_t a0[4], a1[4];
                LDMATRIX_X4(a0[0], a0[1], a0[2], a0[3], lma[0][k16i] + adel);
                LDMATRIX_X4(a1[0], a1[1], a1[2], a1[3], lma[1][k16i] + adel);
                MMAF16(facc[0][0], a0[0], a0[1], a0[2], a0[3], bb[cur][0].x, bb[cur][0].y);
                MMAF16(facc[0][1], a0[0], a0[1], a0[2], a0[3], bb[cur][1].x, bb[cur][1].y);
                MMAF16(facc[0][2], a0[0], a0[1], a0[2], a0[3], bb[cur][2].x, bb[cur][2].y);
                MMAF16(facc[0][3], a0[0], a0[1], a0[2], a0[3], bb[cur][3].x, bb[cur][3].y);
                MMAF16(facc[1][0], a1[0], a1[1], a1[2], a1[3], bb[cur][0].x, bb[cur][0].y);
                MMAF16(facc[1][1], a1[0], a1[1], a1[2], a1[3], bb[cur][1].x, bb[cur][1].y);
                MMAF16(facc[1][2], a1[0], a1[1], a1[2], a1[3], bb[cur][2].x, bb[cur][2].y);
                MMAF16(facc[1][3], a1[0], a1[1], a1[2], a1[3], bb[cur][3].x, bb[cur][3].y);
            }

            // stage A for superstep T+1 spread across subs 0..2
            if (stage_ok) {
                if (sub == 0) run_task(0, T + 1, abn);
                else if (sub == 1) run_task(1, T + 1, abn);
                else if (sub == 2) { if (ntask3) run_task(2, T + 1, abn); }
            }

            // flush fp16 window every 2 substeps
            if (sub & 1) {
#pragma unroll
                for (int ma = 0; ma < 2; ma++)
#pragma unroll
                    for (int na = 0; na < 4; na++) {
                        float2 f0 = __half22float2(*reinterpret_cast<__half2*>(&facc[ma][na][0]));
                        float2 f1 = __half22float2(*reinterpret_cast<__half2*>(&facc[ma][na][1]));
                        acc[ma][na][0] += f0.x; acc[ma][na][1] += f0.y;
                        acc[ma][na][2] += f1.x; acc[ma][na][3] += f1.y;
                        facc[ma][na][0] = 0u; facc[ma][na][1] = 0u;
                    }
            }
        }
    }

    // ---- epilogue (mask rows beyond this tile's valid blocks) ----
    const int l4 = lid >> 2, lc = lid & 3;
#pragma unroll
    for (int ma = 0; ma < 2; ma++) {
        int rl = wr * 32 + ma * 16 + l4;
#pragma unroll
        for (int na = 0; na < 4; na++) {
            int col = wc * 32 + na * 8 + lc * 2;
            if (rl < nrow)
                *(float2*)(outp + (size_t)(o0 * 4 + rl) * 128 + col) =
                    make_float2(acc[ma][na][0], acc[ma][na][1]);
            if (rl + 8 < nrow)
                *(float2*)(outp + (size_t)(o0 * 4 + rl + 8) * 128 + col) =
                    make_float2(acc[ma][na][2], acc[ma][na][3]);
        }
    }
}

// ---------------- launch ----------------
extern "C" void kernel_launch(void* const* d_in, const int* in_sizes, int n_in,
                              void* d_out, int out_size) {
    const float* k  = (const float*)d_in[0];
    const float* v  = (const float*)d_in[1];
    const float* wk = (const float*)d_in[2];
    const float* wv = (const float*)d_in[3];
    const int*   cu = (const int*)d_in[4];
    int nseq = in_sizes[4] - 1;
    int total_tokens = in_sizes[0] / (N_HEADS * H_DIM);

    prep_kernel<<<1025, dim3(32, 8)>>>(cu, nseq, wk, wv, (float*)d_out);

    int ntiles_ub = total_tokens / 256 + MAXSEQ + 1;
    cudaFuncSetAttribute(gemm_kernel, cudaFuncAttributeMaxDynamicSharedMemorySize, SMEM_GEMM);
    gemm_kernel<<<dim3(ntiles_ub, 2), 256, SMEM_GEMM>>>(k, v, (float*)d_out);
}

// round 15
// speedup vs baseline: 1.5749x; 1.5749x over previous
#include <cuda_runtime.h>
#include <cuda_fp16.h>
#include <cstdint>

#define N_HEADS 4
#define H_DIM   128
#define TOK_F   512
#define K_DIM   4096
#define BLK     32
#define STRIDE  16
#define MAXSEQ  256
#define MAXTILE 8192

#define A_SLOT  17408           // 2(dh) x 68 rows x 128B
#define TOK_OFF (2 * A_SLOT)
#define SMEM_GEMM (TOK_OFF + 128)

// ---------------- device scratch ----------------
__device__ int    g_total_out;
__device__ int    g_ntiles;
__device__ int    g_tile_o0[MAXTILE];
__device__ int    g_tile_tok0[MAXTILE];
__device__ int    g_tile_lim[MAXTILE];
__device__ int    g_tile_nrow[MAXTILE];
// B in MMA fragment order: [mat][(atom*256 + chunk)*32 + lane] = {b0,b1}
__device__ uint2  g_wB[2][131072];

static __device__ __forceinline__ uint32_t smem_u32(const void* p) {
    uint32_t a;
    asm("{ .reg .u64 t; cvta.to.shared.u64 t, %1; cvt.u32.u64 %0, t; }" : "=r"(a) : "l"(p));
    return a;
}

#define LDMATRIX_X4(r0, r1, r2, r3, addr) \
    asm volatile("ldmatrix.sync.aligned.m8n8.x4.shared.b16 {%0,%1,%2,%3}, [%4];" \
                 : "=r"(r0), "=r"(r1), "=r"(r2), "=r"(r3) : "r"(addr))

// fp16-accumulate MMA: D,C packed half2 x2
#define MMAF16(c, a0, a1, a2, a3, b0, b1) \
    asm volatile("mma.sync.aligned.m16n8k16.row.col.f16.f16.f16.f16 " \
                 "{%0,%1}, {%2,%3,%4,%5}, {%6,%7}, {%0,%1};" \
                 : "+r"((c)[0]), "+r"((c)[1]) \
                 : "r"(a0), "r"(a1), "r"(a2), "r"(a3), "r"(b0), "r"(b1))

// substep u -> base k16 chunk: j = T + 16*(sub>>1), dh = sub&1
static __device__ __forceinline__ int cb_of(int u) {
    return (u >> 2) * 8 + ((u & 2) << 6) + (u & 1) * 4;
}
// global MMA round g (= u*4 + k16i) -> chunk index
static __device__ __forceinline__ int chunk_of_round(int g) {
    if (g > 255) g = 255;
    return cb_of(g >> 2) + (g & 3);
}

// ---------------- kernel 1: prep = metadata/tile-table + W fragment pack ----------------
__global__ void prep_kernel(const int* __restrict__ cu, int nseq,
                            const float* __restrict__ wk, const float* __restrict__ wv,
                            float* __restrict__ dout) {
    int t = threadIdx.y * 32 + threadIdx.x;
    if (blockIdx.x == 1024) {
        __shared__ int s_ol[MAXSEQ];
        __shared__ int s_cu[MAXSEQ + 1];
        __shared__ int s_ts[MAXSEQ + 1];
        if (t < nseq) {
            int n = cu[t + 1] - cu[t];
            s_ol[t] = (n >= BLK) ? (n - BLK) / STRIDE : 0;
        }
        __syncthreads();
        if (t == 0) {
            int acc = 0, tacc = 0;
            s_cu[0] = 0; s_ts[0] = 0;
            for (int b = 0; b < nseq; b++) {
                acc += s_ol[b];
                tacc += (s_ol[b] + 15) >> 4;
                s_cu[b + 1] = acc;
                s_ts[b + 1] = tacc;
            }
            g_total_out = acc;
            g_ntiles = tacc;
        }
        __syncthreads();
        int total = s_cu[nseq];
        int ntl = s_ts[nseq];
        for (int i = t; i <= nseq; i += 256)
            dout[(size_t)2 * total * 512 + i] = (float)s_cu[i];
        for (int x = t; x < ntl; x += 256) {
            int b = 0;
            while (s_ts[b + 1] <= x) b++;
            int ti = x - s_ts[b];
            int o0 = s_cu[b] + ti * 16;
            int ol = s_cu[b + 1] - o0;
            g_tile_o0[x]   = o0;
            g_tile_tok0[x] = cu[b] + ti * 256;
            g_tile_lim[x]  = cu[b + 1] - 16;
            g_tile_nrow[x] = (ol < 16 ? ol : 16) * 4;
        }
        return;
    }
    // fragment-pack W: idx -> (atom a, chunk c, lane l)
    int z   = blockIdx.x >> 9;
    int rem = blockIdx.x & 511;
    const float* w = z ? wv : wk;
    int idx = rem * 256 + t;                  // 0..131071
    int a = idx >> 13;
    int c = (idx >> 5) & 255;
    int l = idx & 31;
    int n  = 8 * a + (l >> 2);
    int k1 = 16 * c + 2 * (l & 3);
    float v0 = w[(size_t)k1 * H_DIM + n];
    float v1 = w[(size_t)(k1 + 1) * H_DIM + n];
    float v2 = w[(size_t)(k1 + 8) * H_DIM + n];
    float v3 = w[(size_t)(k1 + 9) * H_DIM + n];
    __half2 h0 = __floats2half2_rn(v0, v1);
    __half2 h1 = __floats2half2_rn(v2, v3);
    uint2 u;
    u.x = *reinterpret_cast<uint32_t*>(&h0);
    u.y = *reinterpret_cast<uint32_t*>(&h1);
    g_wB[z][idx] = u;
}

// ---------------- kernel 2: HMMA GEMM, B direct-from-L2, split A staging ----------------
// 256 thr = 8 warps in 2(M) x 4(N); warp tile 32x32; CTA tile 64x128.
// A: token-dedup smem staging, ONE __syncthreads per superstep; staging LDGs
//    issued one substep before their cvt+STS (hides gmem latency).
// B: LDG.64 fragments, full-substep register ring bb[16] (distance 4 rounds).
__global__ __launch_bounds__(256, 2)
void gemm_kernel(const float* __restrict__ kin, const float* __restrict__ vin,
                 float* __restrict__ dout) {
    extern __shared__ __align__(128) char smem[];
    const uint32_t sa = smem_u32(smem);            // A: 2 slots x 17408
    int* s_tok = (int*)(smem + TOK_OFF);

    const int tid = threadIdx.x;
    const int wid = tid >> 5;
    const int lid = tid & 31;
    const int bx  = blockIdx.x;
    if (bx >= g_ntiles) return;
    const int total_out = g_total_out;
    const int o0   = g_tile_o0[bx];
    const int tok0 = g_tile_tok0[bx];
    const int lim  = g_tile_lim[bx];
    const int nrow = g_tile_nrow[bx];

    const int mat = blockIdx.y;
    const float* __restrict__ x = mat ? vin : kin;
    const uint2* __restrict__ wB = g_wB[mat];
    float* __restrict__ outp = dout + (size_t)mat * (size_t)total_out * 512;

    if (tid < 17) {
        int tk = tok0 + 16 * tid;
        s_tok[tid] = tk < lim ? tk : lim;
    }
    __syncthreads();

    // ---- A staging tasks: tau = sr*8 + dh*4 + cpair ----
    int      sgoff[3];
    uint32_t sadr[3];
    const int ntask3 = (tid < 32) ? 1 : 0;
#pragma unroll
    for (int tsk = 0; tsk < 3; tsk++) {
        int tau = tsk * 256 + tid;
        if (tau >= 544) tau = 543;
        int sr = tau >> 3, dh = (tau >> 2) & 1, cp = tau & 3;
        int i = sr >> 2, h = sr & 3;
        sgoff[tsk] = s_tok[i] * TOK_F + h * H_DIM + dh * 64 + cp * 16;
        sadr[tsk]  = (uint32_t)(dh * 8704 + sr * 128 + (((2 * cp) ^ (sr & 7)) * 16));
    }

    // ---- ldmatrix A addresses ----
    const int wr = wid >> 2;       // M position 0..1
    const int wc = wid & 3;        // N position 0..3
    const int g  = lid >> 3;
    const int l7 = lid & 7;
    uint32_t lma[2][4];
    int hidelta[4];
#pragma unroll
    for (int k16i = 0; k16i < 4; k16i++) {
        int c = 2 * k16i + (g >> 1);
        hidelta[k16i] = 512 + (((c ^ l7) & 4) ? -64 : 64);
#pragma unroll
        for (int ma = 0; ma < 2; ma++) {
            int sr = wr * 32 + ma * 16 + (g & 1) * 8 + l7;
            lma[ma][k16i] = sa + (uint32_t)(sr * 128 + ((c ^ (sr & 7)) * 16));
        }
    }

    // ---- B fragment element bases: atom a = wc*4 + p ----
    int bbase[4];
#pragma unroll
    for (int p = 0; p < 4; p++)
        bbase[p] = ((wc * 4 + p) << 13) + lid;

    float acc[2][4][4];
    uint32_t facc[2][4][2];
#pragma unroll
    for (int ma = 0; ma < 2; ma++)
#pragma unroll
        for (int na = 0; na < 4; na++) {
#pragma unroll
            for (int e = 0; e < 4; e++) acc[ma][na][e] = 0.f;
            facc[ma][na][0] = 0u; facc[ma][na][1] = 0u;
        }

    // full staging task (prologue + task2): 16 fp32 LDG -> cvt -> 2 uint4 STS
    auto run_task = [&](int tsk, int jnext, uint32_t abuf) {
        const float* p = x + sgoff[tsk] + jnext * TOK_F;
        float4 f0 = *(const float4*)(p);
        float4 f1 = *(const float4*)(p + 4);
        float4 f2 = *(const float4*)(p + 8);
        float4 f3 = *(const float4*)(p + 12);
        __half2 h;
        uint4 u1, u2;
        h = __floats2half2_rn(f0.x, f0.y); u1.x = *(uint32_t*)&h;
        h = __floats2half2_rn(f0.z, f0.w); u1.y = *(uint32_t*)&h;
        h = __floats2half2_rn(f1.x, f1.y); u1.z = *(uint32_t*)&h;
        h = __floats2half2_rn(f1.z, f1.w); u1.w = *(uint32_t*)&h;
        h = __floats2half2_rn(f2.x, f2.y); u2.x = *(uint32_t*)&h;
        h = __floats2half2_rn(f2.z, f2.w); u2.y = *(uint32_t*)&h;
        h = __floats2half2_rn(f3.x, f3.y); u2.z = *(uint32_t*)&h;
        h = __floats2half2_rn(f3.z, f3.w); u2.w = *(uint32_t*)&h;
        uint32_t a1 = abuf + sadr[tsk];
        *(uint4*)(smem + a1) = u1;
        *(uint4*)(smem + (a1 ^ 16)) = u2;
    };

    // split staging: half = 8 floats (one swizzled uint4)
    float4 hv0, hv1;
    auto load_half = [&](int tsk, int q, int jnext) {
        const float* p = x + sgoff[tsk] + jnext * TOK_F + q * 8;
        hv0 = *(const float4*)(p);
        hv1 = *(const float4*)(p + 4);
    };
    auto store_half = [&](int tsk, int q, uint32_t abuf) {
        __half2 h;
        uint4 u;
        h = __floats2half2_rn(hv0.x, hv0.y); u.x = *(uint32_t*)&h;
        h = __floats2half2_rn(hv0.z, hv0.w); u.y = *(uint32_t*)&h;
        h = __floats2half2_rn(hv1.x, hv1.y); u.z = *(uint32_t*)&h;
        h = __floats2half2_rn(hv1.z, hv1.w); u.w = *(uint32_t*)&h;
        *(uint4*)(smem + (abuf + (sadr[tsk] ^ (uint32_t)(q * 16)))) = u;
    };

    // ---- prologue: stage A superstep 0 (full tasks); preload B substep 0 ----
    run_task(0, 0, 0);
    run_task(1, 0, 0);
    if (ntask3) run_task(2, 0, 0);

    uint2 bb[16];                              // one-substep B ring (distance 4 rounds)
    {
        const int cb0 = cb_of(0);
#pragma unroll
        for (int k16i = 0; k16i < 4; k16i++)
#pragma unroll
            for (int p = 0; p < 4; p++)
                bb[k16i * 4 + p] = wB[bbase[p] + (cb0 + k16i) * 32];
    }

#pragma unroll 1
    for (int T = 0; T < 16; T++) {
        __syncthreads();   // publish A slot T&1; slot (T+1)&1 free (readers were T-1)
        const uint32_t ab  = (uint32_t)((T & 1) * A_SLOT);
        const uint32_t abn = (uint32_t)(((T + 1) & 1) * A_SLOT);
        const int stage_ok = (T + 1 < 16);

#pragma unroll
        for (int sub = 0; sub < 4; sub++) {
            const int u = T * 4 + sub;
            const int unext = (u + 1 < 64) ? u + 1 : u;
            const int cbn = cb_of(unext);
            const uint32_t adh = ab + (uint32_t)((sub & 1) * 8704);
            const int hi = sub >> 1;

#pragma unroll
            for (int k16i = 0; k16i < 4; k16i++) {
                uint32_t adel = adh + (hi ? (uint32_t)hidelta[k16i] : 0u);
                uint32_t a0[4], a1[4];
                LDMATRIX_X4(a0[0], a0[1], a0[2], a0[3], lma[0][k16i] + adel);
                LDMATRIX_X4(a1[0], a1[1], a1[2], a1[3], lma[1][k16i] + adel);
                MMAF16(facc[0][0], a0[0], a0[1], a0[2], a0[3], bb[k16i*4+0].x, bb[k16i*4+0].y);
                MMAF16(facc[0][1], a0[0], a0[1], a0[2], a0[3], bb[k16i*4+1].x, bb[k16i*4+1].y);
                MMAF16(facc[0][2], a0[0], a0[1], a0[2], a0[3], bb[k16i*4+2].x, bb[k16i*4+2].y);
                MMAF16(facc[0][3], a0[0], a0[1], a0[2], a0[3], bb[k16i*4+3].x, bb[k16i*4+3].y);
                MMAF16(facc[1][0], a1[0], a1[1], a1[2], a1[3], bb[k16i*4+0].x, bb[k16i*4+0].y);
                MMAF16(facc[1][1], a1[0], a1[1], a1[2], a1[3], bb[k16i*4+1].x, bb[k16i*4+1].y);
                MMAF16(facc[1][2], a1[0], a1[1], a1[2], a1[3], bb[k16i*4+2].x, bb[k16i*4+2].y);
                MMAF16(facc[1][3], a1[0], a1[1], a1[2], a1[3], bb[k16i*4+3].x, bb[k16i*4+3].y);
                // prefetch next substep's B fragments into the just-freed slots
#pragma unroll
                for (int p = 0; p < 4; p++)
                    bb[k16i * 4 + p] = wB[bbase[p] + (cbn + k16i) * 32];
            }

            // split A staging for superstep T+1: LDG one substep ahead of cvt+STS
            if (stage_ok) {
                if (sub == 0) {
                    load_half(0, 0, T + 1);
                } else if (sub == 1) {
                    store_half(0, 0, abn);
                    load_half(0, 1, T + 1);
                } else if (sub == 2) {
                    store_half(0, 1, abn);
                    load_half(1, 0, T + 1);
                    if (ntask3) run_task(2, T + 1, abn);
                } else {
                    store_half(1, 0, abn);
                    load_half(1, 1, T + 1);
                    store_half(1, 1, abn);      // exposed (last half)
                }
            }

            // flush fp16 window every 2 substeps
            if (sub & 1) {
#pragma unroll
                for (int ma = 0; ma < 2; ma++)
#pragma unroll
                    for (int na = 0; na < 4; na++) {
                        float2 f0 = __half22float2(*reinterpret_cast<__half2*>(&facc[ma][na][0]));
                        float2 f1 = __half22float2(*reinterpret_cast<__half2*>(&facc[ma][na][1]));
                        acc[ma][na][0] += f0.x; acc[ma][na][1] += f0.y;
                        acc[ma][na][2] += f1.x; acc[ma][na][3] += f1.y;
                        facc[ma][na][0] = 0u; facc[ma][na][1] = 0u;
                    }
            }
        }
    }

    // ---- epilogue (mask rows beyond this tile's valid blocks) ----
    const int l4 = lid >> 2, lc = lid & 3;
#pragma unroll
    for (int ma = 0; ma < 2; ma++) {
        int rl = wr * 32 + ma * 16 + l4;
#pragma unroll
        for (int na = 0; na < 4; na++) {
            int col = wc * 32 + na * 8 + lc * 2;
            if (rl < nrow)
                *(float2*)(outp + (size_t)(o0 * 4 + rl) * 128 + col) =
                    make_float2(acc[ma][na][0], acc[ma][na][1]);
            if (rl + 8 < nrow)
                *(float2*)(outp + (size_t)(o0 * 4 + rl + 8) * 128 + col) =
                    make_float2(acc[ma][na][2], acc[ma][na][3]);
        }
    }
}

// ---------------- launch ----------------
extern "C" void kernel_launch(void* const* d_in, const int* in_sizes, int n_in,
                              void* d_out, int out_size) {
    const float* k  = (const float*)d_in[0];
    const float* v  = (const float*)d_in[1];
    const float* wk = (const float*)d_in[2];
    const float* wv = (const float*)d_in[3];
    const int*   cu = (const int*)d_in[4];
    int nseq = in_sizes[4] - 1;
    int total_tokens = in_sizes[0] / (N_HEADS * H_DIM);

    prep_kernel<<<1025, dim3(32, 8)>>>(cu, nseq, wk, wv, (float*)d_out);

    int ntiles_ub = total_tokens / 256 + MAXSEQ + 1;
    cudaFuncSetAttribute(gemm_kernel, cudaFuncAttributeMaxDynamicSharedMemorySize, SMEM_GEMM);
    gemm_kernel<<<dim3(ntiles_ub, 2), 256, SMEM_GEMM>>>(k, v, (float*)d_out);
}